// round 3
// baseline (speedup 1.0000x reference)
#include <cuda_runtime.h>
#include <cuda_fp16.h>
#include <cuda_fp8.h>
#include <cstdint>

// ---------------- Problem constants (fixed-shape bench) ----------------
#define T_MAX   8192
#define K_DIM   4096
#define O_DIM   4096
#define FP8_MAX 448.0f

// ---------------- GEMM tiling (mma.sync sm80-style) ----------------
#define BM 128
#define BN 128
#define BK 32                    // halfs per k-chunk
#define STAGES 4
#define KTOT   (K_DIM / BK)      // 128
#define PAD    8                 // halfs of row padding (16B, keeps cp.async alignment)
#define LDROW  (BK + PAD)        // 40 halfs = 80 bytes per smem row
#define A_STAGE_BYTES (BM * LDROW * 2)   // 10240
#define B_STAGE_BYTES (BN * LDROW * 2)   // 10240
#define STAGE_BYTES   (A_STAGE_BYTES + B_STAGE_BYTES)
#define SMEM_BYTES    (STAGES * STAGE_BYTES)   // 81920

// ---------------- Scratch (static device globals; no allocation) ----------------
__device__ __align__(1024) __half g_xq[(size_t)T_MAX * K_DIM];   // 64 MB
__device__ __align__(1024) __half g_wd[(size_t)O_DIM * K_DIM];   // 32 MB
__device__ float g_xs[T_MAX];

// ---------------- PTX helpers (base ISA only; no tcgen05/TMEM) ----------------
__device__ __forceinline__ uint32_t smem_u32(const void* p) {
    uint32_t a;
    asm("{ .reg .u64 t; cvta.to.shared.u64 t, %1; cvt.u32.u64 %0, t; }" : "=r"(a) : "l"(p));
    return a;
}

#define CP_ASYNC_CG16(saddr, gptr) \
    asm volatile("cp.async.cg.shared.global [%0], [%1], 16;" :: "r"(saddr), "l"(gptr) : "memory")
#define CP_COMMIT() asm volatile("cp.async.commit_group;" ::: "memory")
#define CP_WAIT(n)  asm volatile("cp.async.wait_group %0;" :: "n"(n) : "memory")

#define LDSM_X4(r, addr) \
    asm volatile("ldmatrix.sync.aligned.m8n8.x4.shared.b16 {%0,%1,%2,%3}, [%4];" \
        : "=r"((r)[0]), "=r"((r)[1]), "=r"((r)[2]), "=r"((r)[3]) : "r"(addr))

#define MMA16816(d, a, b0, b1) \
    asm volatile("mma.sync.aligned.m16n8k16.row.col.f32.f16.f16.f32 " \
        "{%0,%1,%2,%3}, {%4,%5,%6,%7}, {%8,%9}, {%0,%1,%2,%3};" \
        : "+f"((d)[0]), "+f"((d)[1]), "+f"((d)[2]), "+f"((d)[3]) \
        : "r"((a)[0]), "r"((a)[1]), "r"((a)[2]), "r"((a)[3]), "r"(b0), "r"(b1))

// ---------------- Kernel 1: per-token amax + e4m3 round-trip -> fp16 ----------------
__device__ __forceinline__ __half2 fp8_roundtrip_h2(float a, float b) {
    float2 f2 = make_float2(a, b);
    __nv_fp8x2_storage_t p = __nv_cvt_float2_to_fp8x2(f2, __NV_SATFINITE, __NV_E4M3);
    __half2_raw hr = __nv_cvt_fp8x2_to_halfraw2(p, __NV_E4M3);
    return *reinterpret_cast<__half2*>(&hr);
}

__global__ void __launch_bounds__(256) quant_x_kernel(
    const float* __restrict__ x, __half* __restrict__ xq, float* __restrict__ xs)
{
    int row = blockIdx.x;
    int tid = threadIdx.x;
    const float4* xr = reinterpret_cast<const float4*>(x + (size_t)row * K_DIM);
    float4 v[4];
    float am = 0.0f;
#pragma unroll
    for (int j = 0; j < 4; j++) {
        v[j] = xr[tid + j * 256];
        am = fmaxf(am, fmaxf(fmaxf(fabsf(v[j].x), fabsf(v[j].y)),
                             fmaxf(fabsf(v[j].z), fabsf(v[j].w))));
    }
#pragma unroll
    for (int o = 16; o > 0; o >>= 1)
        am = fmaxf(am, __shfl_xor_sync(0xffffffffu, am, o));
    __shared__ float red[8];
    if ((tid & 31) == 0) red[tid >> 5] = am;
    __syncthreads();
    float m = red[0];
#pragma unroll
    for (int i = 1; i < 8; i++) m = fmaxf(m, red[i]);
    m = fmaxf(m, 1e-12f);
    float scale = m / FP8_MAX;       // matches reference x_scale
    if (tid == 0) xs[row] = scale;
    float rs = 1.0f / scale;
    __half2* outp = reinterpret_cast<__half2*>(xq + (size_t)row * K_DIM);
#pragma unroll
    for (int j = 0; j < 4; j++) {
        int f = tid + j * 256;
        outp[2 * f + 0] = fp8_roundtrip_h2(v[j].x * rs, v[j].y * rs);
        outp[2 * f + 1] = fp8_roundtrip_h2(v[j].z * rs, v[j].w * rs);
    }
}

// ---------------- Kernel 2: blockwise weight dequant -> fp16 ----------------
__global__ void __launch_bounds__(256) dequant_w_kernel(
    const float* __restrict__ w, const float* __restrict__ ws, __half* __restrict__ wd)
{
    size_t idx = ((size_t)blockIdx.x * blockDim.x + threadIdx.x) * 4;
    int o = (int)(idx >> 12);            // / 4096
    int i = (int)(idx & 4095);
    float s = ws[(o >> 7) * (K_DIM / 128) + (i >> 7)];
    float4 v = *reinterpret_cast<const float4*>(w + idx);
    __half2 h0 = __floats2half2_rn(v.x * s, v.y * s);
    __half2 h1 = __floats2half2_rn(v.z * s, v.w * s);
    __half2* p = reinterpret_cast<__half2*>(wd + idx);
    p[0] = h0;
    p[1] = h1;
}

// ---------------- Kernel 3: f16 mma.sync GEMM, 128x128x32, 4-stage cp.async ----------------
__global__ void __launch_bounds__(256, 2) gemm_kernel(
    float* __restrict__ out, const float* __restrict__ xs,
    const __half* __restrict__ A,   // [T, K] fp16 (quantized x)
    const __half* __restrict__ B,   // [O, K] fp16 (dequant weight)
    int ntiles_n)
{
    extern __shared__ char smem[];
    const uint32_t smA = smem_u32(smem);
    const uint32_t smB = smA + STAGES * A_STAGE_BYTES;

    const int tid  = threadIdx.x;
    const int lane = tid & 31;
    const int wid  = tid >> 5;
    const int wm   = wid & 1;    // 2 warp rows (64 M each)
    const int wn   = wid >> 1;   // 4 warp cols (32 N each)

    const int ntile = blockIdx.x % ntiles_n;
    const int mtile = blockIdx.x / ntiles_n;

    const __half* gA = A + (size_t)(mtile * BM) * K_DIM;
    const __half* gB = B + (size_t)(ntile * BN) * K_DIM;

    // per-thread cp.async coords: chunk = tid (+256); row = chunk/4, 16B col = chunk%4
    const int lrow = tid >> 2;
    const int lcc  = tid & 3;

    float acc[4][4][4];
#pragma unroll
    for (int a = 0; a < 4; a++)
#pragma unroll
        for (int b = 0; b < 4; b++)
#pragma unroll
            for (int c = 0; c < 4; c++) acc[a][b][c] = 0.0f;

    // ldmatrix per-lane base addresses (half units -> bytes)
    const uint32_t aBase = smA + (uint32_t)(((wm * 64 + (lane & 15)) * LDROW + (lane >> 4) * 8) * 2);
    const uint32_t bBase = smB + (uint32_t)(((wn * 32 + (lane & 15)) * LDROW + (lane >> 4) * 8) * 2);

    auto load_stage = [&](int s, int kt) {
        const uint32_t sa = smA + s * A_STAGE_BYTES;
        const uint32_t sb = smB + s * B_STAGE_BYTES;
        const __half* ga = gA + kt * BK;
        const __half* gb = gB + kt * BK;
#pragma unroll
        for (int i = 0; i < 2; i++) {
            int row = lrow + i * 64;
            uint32_t so = (uint32_t)(row * (LDROW * 2) + lcc * 16);
            CP_ASYNC_CG16(sa + so, ga + (size_t)row * K_DIM + lcc * 8);
            CP_ASYNC_CG16(sb + so, gb + (size_t)row * K_DIM + lcc * 8);
        }
    };

    // prologue: 3 stages in flight
#pragma unroll
    for (int s = 0; s < STAGES - 1; s++) {
        load_stage(s, s);
        CP_COMMIT();
    }

    for (int kt = 0; kt < KTOT; kt++) {
        CP_WAIT(2);          // stage kt arrived (kt+1, kt+2 may still be pending)
        __syncthreads();     // visibility of other threads' async copies; also guards overwrite below

        int nk = kt + (STAGES - 1);
        if (nk < KTOT) load_stage((nk & (STAGES - 1)), nk);
        CP_COMMIT();         // commit every iter (possibly empty) to keep group accounting uniform

        const int s = kt & (STAGES - 1);
        const uint32_t sa = aBase + s * A_STAGE_BYTES;
        const uint32_t sb = bBase + s * B_STAGE_BYTES;
#pragma unroll
        for (int ks = 0; ks < 2; ks++) {
            const uint32_t ka = sa + ks * 32;   // 16 halfs
            const uint32_t kb = sb + ks * 32;
            uint32_t af[4][4];
            uint32_t bf[2][4];
#pragma unroll
            for (int mt = 0; mt < 4; mt++) LDSM_X4(af[mt], ka + mt * 16 * (LDROW * 2));
#pragma unroll
            for (int pt = 0; pt < 2; pt++) LDSM_X4(bf[pt], kb + pt * 16 * (LDROW * 2));
#pragma unroll
            for (int mt = 0; mt < 4; mt++) {
#pragma unroll
                for (int nt = 0; nt < 4; nt++) {
                    const int pt = nt >> 1, od = nt & 1;
                    MMA16816(acc[mt][nt], af[mt], bf[pt][od], bf[pt][od + 2]);
                }
            }
        }
    }

    // epilogue: scale by per-token x_scale, store f32
    const int rowbase = mtile * BM + wm * 64 + (lane >> 2);
    const int colbase = ntile * BN + wn * 32 + (lane & 3) * 2;
#pragma unroll
    for (int mt = 0; mt < 4; mt++) {
        const int r0 = rowbase + mt * 16;
        const float s0 = xs[r0];
        const float s1 = xs[r0 + 8];
        float* o0 = out + (size_t)r0 * O_DIM + colbase;
        float* o1 = o0 + (size_t)8 * O_DIM;
#pragma unroll
        for (int nt = 0; nt < 4; nt++) {
            float2 v0 = make_float2(acc[mt][nt][0] * s0, acc[mt][nt][1] * s0);
            float2 v1 = make_float2(acc[mt][nt][2] * s1, acc[mt][nt][3] * s1);
            *reinterpret_cast<float2*>(o0 + nt * 8) = v0;
            *reinterpret_cast<float2*>(o1 + nt * 8) = v1;
        }
    }
}

// ---------------- Launch ----------------
extern "C" void kernel_launch(void* const* d_in, const int* in_sizes, int n_in,
                              void* d_out, int out_size)
{
    const float* x  = (const float*)d_in[0];
    const float* w  = (const float*)d_in[1];
    const float* ws = (const float*)d_in[2];
    float* out = (float*)d_out;

    const int K = K_DIM;
    const int T = in_sizes[0] / K;   // 8192
    const int O = in_sizes[1] / K;   // 4096

    void *pxq = nullptr, *pwd = nullptr, *pxs = nullptr;
    cudaGetSymbolAddress(&pxq, g_xq);
    cudaGetSymbolAddress(&pwd, g_wd);
    cudaGetSymbolAddress(&pxs, g_xs);

    quant_x_kernel<<<T, 256>>>(x, (__half*)pxq, (float*)pxs);
    dequant_w_kernel<<<(int)(((size_t)O * K / 4) / 256), 256>>>(w, ws, (__half*)pwd);

    cudaFuncSetAttribute(gemm_kernel, cudaFuncAttributeMaxDynamicSharedMemorySize, SMEM_BYTES);

    const int ntiles_n = O / BN;                 // 32
    const int grid = (T / BM) * ntiles_n;        // 2048
    gemm_kernel<<<grid, 256, SMEM_BYTES>>>(out, (float*)pxs, (const __half*)pxq,
                                           (const __half*)pwd, ntiles_n);
}